// round 4
// baseline (speedup 1.0000x reference)
#include <cuda_runtime.h>
#include <math.h>

typedef unsigned long long ull;

// ---- problem constants ----
#define BB  16
#define HH  384
#define WW  512
#define HPP 191
#define WPP 255
#define H2D 189
#define W2D 253
#define H3D 187
#define W3D 251
#define NPIX (H3D*W3D)   // 46937
#define NEGV (-1e30f)
#define THRESH_V 0.6f
#define KPICKS 128
#define CAP 5600
#define SP  260          // padded row stride (mult of 4)
#define PH  196          // padded plane height

// ---- scratch (zero-initialized device globals; padding stays deterministic) ----
__device__ __align__(16) float  g_pool[BB*10*PH*SP];
__device__ __align__(16) float  g_h2[BB*16*PH*SP];
__device__ int    g_cnt[BB];
__device__ int    g_cand[BB*NPIX];      // packed (y<<16)|x
__device__ float  g_cand_sc[BB*NPIX];
__device__ float4 g_cand_reg[BB*NPIX];

// ---- f32x2 helpers ----
__device__ __forceinline__ ull pack2(float lo, float hi){
    ull r; asm("mov.b64 %0, {%1, %2};" : "=l"(r) : "f"(lo), "f"(hi)); return r;
}
__device__ __forceinline__ void unpack2(ull v, float &lo, float &hi){
    asm("mov.b64 {%0, %1}, %2;" : "=f"(lo), "=f"(hi) : "l"(v));
}
__device__ __forceinline__ void fma2(ull &d, ull a, ull b){
    asm("fma.rn.f32x2 %0, %1, %2, %0;" : "+l"(d) : "l"(a), "l"(b));
}

// ============================================================
__global__ void k0_zero(){
    if (threadIdx.x < BB) g_cnt[threadIdx.x] = 0;
}

// ============================================================
// K1: normalize + conv1(3x3,3->10) + PReLU + maxpool2x2
// 1 thread = 1 pooled pixel (4 conv px), oc-pair packing
// ============================================================
__global__ __launch_bounds__(256) void k1_conv1_pool(const float* __restrict__ im,
                              const float* __restrict__ w,   // (10,3,3,3)
                              const float* __restrict__ b,
                              const float* __restrict__ p)
{
    __shared__ __align__(16) ull sw[135];   // [(c*9+k)*5 + q]
    __shared__ float sb[10], sp[10];
    int tid = threadIdx.y * 32 + threadIdx.x;
    for (int i = tid; i < 135; i += 256){
        int ck = i / 5, q = i % 5;
        sw[i] = pack2(w[(2*q)*27 + ck], w[(2*q+1)*27 + ck]);
    }
    if (tid < 10){ sb[tid] = b[tid]; sp[tid] = p[tid]; }
    __syncthreads();

    int ox = blockIdx.x * 32 + threadIdx.x;
    int oy = blockIdx.y * 8  + threadIdx.y;
    int bb = blockIdx.z;
    if (ox >= WPP || oy >= HPP) return;

    ull acc[4][5];
#pragma unroll
    for (int q = 0; q < 5; q++){
        ull bi = pack2(sb[2*q], sb[2*q+1]);
        acc[0][q] = bi; acc[1][q] = bi; acc[2][q] = bi; acc[3][q] = bi;
    }

#pragma unroll
    for (int c = 0; c < 3; c++){
        const float* base = im + ((bb*3 + c)*HH + 2*oy)*WW + 2*ox;
        ull du[4][4];
#pragma unroll
        for (int r = 0; r < 4; r++){
            float2 u01 = *reinterpret_cast<const float2*>(base + r*WW);
            float2 u23 = *reinterpret_cast<const float2*>(base + r*WW + 2);
            float v0 = (u01.x - 127.5f)*0.0078125f;
            float v1 = (u01.y - 127.5f)*0.0078125f;
            float v2 = (u23.x - 127.5f)*0.0078125f;
            float v3 = (u23.y - 127.5f)*0.0078125f;
            du[r][0] = pack2(v0,v0); du[r][1] = pack2(v1,v1);
            du[r][2] = pack2(v2,v2); du[r][3] = pack2(v3,v3);
        }
#pragma unroll
        for (int ky = 0; ky < 3; ky++)
#pragma unroll
        for (int kx = 0; kx < 3; kx++){
            const ull* wq = &sw[(c*9 + ky*3 + kx)*5];
#pragma unroll
            for (int q = 0; q < 5; q++){
                ull wv = wq[q];
                fma2(acc[0][q], du[ky  ][kx  ], wv);
                fma2(acc[1][q], du[ky  ][kx+1], wv);
                fma2(acc[2][q], du[ky+1][kx  ], wv);
                fma2(acc[3][q], du[ky+1][kx+1], wv);
            }
        }
    }
#pragma unroll
    for (int q = 0; q < 5; q++){
        float h[4][2];
#pragma unroll
        for (int pp = 0; pp < 4; pp++) unpack2(acc[pp][q], h[pp][0], h[pp][1]);
#pragma unroll
        for (int s = 0; s < 2; s++){
            int oc = 2*q + s;
            float al = sp[oc];
            float m = -INFINITY;
#pragma unroll
            for (int pp = 0; pp < 4; pp++){
                float v = h[pp][s];
                v = v > 0.f ? v : al*v;
                m = fmaxf(m, v);
            }
            g_pool[((bb*10 + oc)*PH + oy)*SP + ox] = m;
        }
    }
}

// ============================================================
// K2: conv2(3x3,10->16) + PReLU
// 1 thread = 4 px, full 16 oc as 8 ocpairs (LDS.128:FMA2 = 1:8)
// ============================================================
__global__ __launch_bounds__(256) void k2_conv2(const float* __restrict__ w,  // (16,10,3,3)
                         const float* __restrict__ b,
                         const float* __restrict__ p)
{
    __shared__ __align__(16) ull sw[720];   // [(c*9+k)*8 + q]
    __shared__ float sb[16], sp[16];
    int tid = threadIdx.y * 32 + threadIdx.x;
    for (int i = tid; i < 720; i += 256){
        int ck = i >> 3, q = i & 7;
        sw[i] = pack2(w[(2*q)*90 + ck], w[(2*q+1)*90 + ck]);
    }
    if (tid < 16){ sb[tid] = b[tid]; sp[tid] = p[tid]; }
    __syncthreads();

    int x0 = blockIdx.x * 128 + threadIdx.x * 4;  // <= 252; reads <= 257 < SP
    int oy = blockIdx.y * 8   + threadIdx.y;      // <= 191; reads rows <= 193 < PH
    int bb = blockIdx.z;

    ull acc[4][8];
#pragma unroll
    for (int q = 0; q < 8; q++){
        ull bi = pack2(sb[2*q], sb[2*q+1]);
        acc[0][q] = bi; acc[1][q] = bi; acc[2][q] = bi; acc[3][q] = bi;
    }

    for (int c = 0; c < 10; c++){
        const float* base = g_pool + ((bb*10 + c)*PH + oy)*SP + x0;
        ull du[3][6];
#pragma unroll
        for (int r = 0; r < 3; r++){
            float4 a4 = *reinterpret_cast<const float4*>(base + r*SP);
            float2 b2 = *reinterpret_cast<const float2*>(base + r*SP + 4);
            du[r][0] = pack2(a4.x,a4.x); du[r][1] = pack2(a4.y,a4.y);
            du[r][2] = pack2(a4.z,a4.z); du[r][3] = pack2(a4.w,a4.w);
            du[r][4] = pack2(b2.x,b2.x); du[r][5] = pack2(b2.y,b2.y);
        }
#pragma unroll
        for (int ky = 0; ky < 3; ky++)
#pragma unroll
        for (int kx = 0; kx < 3; kx++){
            const ulonglong2* wp = reinterpret_cast<const ulonglong2*>(&sw[(c*9 + ky*3 + kx)*8]);
#pragma unroll
            for (int g = 0; g < 4; g++){
                ulonglong2 wv = wp[g];
#pragma unroll
                for (int pp = 0; pp < 4; pp++){
                    fma2(acc[pp][2*g],   du[ky][kx+pp], wv.x);
                    fma2(acc[pp][2*g+1], du[ky][kx+pp], wv.y);
                }
            }
        }
    }
#pragma unroll
    for (int q = 0; q < 8; q++){
        float v[4][2];
#pragma unroll
        for (int pp = 0; pp < 4; pp++) unpack2(acc[pp][q], v[pp][0], v[pp][1]);
#pragma unroll
        for (int s = 0; s < 2; s++){
            int oc = 2*q + s;
            float al = sp[oc];
            float4 o;
            float t0 = v[0][s]; o.x = t0 > 0.f ? t0 : al*t0;
            float t1 = v[1][s]; o.y = t1 > 0.f ? t1 : al*t1;
            float t2 = v[2][s]; o.z = t2 > 0.f ? t2 : al*t2;
            float t3 = v[3][s]; o.w = t3 > 0.f ? t3 : al*t3;
            *reinterpret_cast<float4*>(&g_h2[((bb*16 + oc)*PH + oy)*SP + x0]) = o;
        }
    }
}

// ============================================================
// K3: conv3(3x3,16->32)+PReLU + fused 1x1 heads + append
// 1 thread = 4 px, full 32 oc as 16 ocpairs (LDS.128:FMA2 = 1:8)
// ============================================================
__global__ __launch_bounds__(256) void k3_conv3_heads(const float* __restrict__ w3, // (32,16,3,3)
                               const float* __restrict__ b3,
                               const float* __restrict__ p3,
                               const float* __restrict__ w41, const float* __restrict__ b41,
                               const float* __restrict__ w42, const float* __restrict__ b42)
{
    __shared__ __align__(16) ull sw[2304];  // [(c*9+k)*16 + q]
    __shared__ float sb[32], sp[32];
    __shared__ float sw41[64], sw42[128], sb41[2], sb42[4];
    int tid = threadIdx.y * 32 + threadIdx.x;
    for (int i = tid; i < 2304; i += 256){
        int ck = i >> 4, q = i & 15;
        sw[i] = pack2(w3[(2*q)*144 + ck], w3[(2*q+1)*144 + ck]);
    }
    if (tid < 32){ sb[tid] = b3[tid]; sp[tid] = p3[tid]; }
    if (tid < 64)  sw41[tid] = w41[tid];
    if (tid < 128) sw42[tid] = w42[tid];
    if (tid < 2)   sb41[tid] = b41[tid];
    if (tid < 4)   sb42[tid] = b42[tid];
    __syncthreads();

    int x0 = blockIdx.x * 128 + threadIdx.x * 4;  // <= 252; reads <= 257 < SP
    int oy = blockIdx.y * 8   + threadIdx.y;      // <= 191; reads rows <= 193 < PH
    int bb = blockIdx.z;

    ull acc[4][16];
#pragma unroll
    for (int q = 0; q < 16; q++){
        ull bi = pack2(sb[2*q], sb[2*q+1]);
        acc[0][q] = bi; acc[1][q] = bi; acc[2][q] = bi; acc[3][q] = bi;
    }

    for (int c = 0; c < 16; c++){
        const float* base = g_h2 + ((bb*16 + c)*PH + oy)*SP + x0;
        ull du[3][6];
#pragma unroll
        for (int r = 0; r < 3; r++){
            float4 a4 = *reinterpret_cast<const float4*>(base + r*SP);
            float2 b2 = *reinterpret_cast<const float2*>(base + r*SP + 4);
            du[r][0] = pack2(a4.x,a4.x); du[r][1] = pack2(a4.y,a4.y);
            du[r][2] = pack2(a4.z,a4.z); du[r][3] = pack2(a4.w,a4.w);
            du[r][4] = pack2(b2.x,b2.x); du[r][5] = pack2(b2.y,b2.y);
        }
#pragma unroll
        for (int ky = 0; ky < 3; ky++)
#pragma unroll
        for (int kx = 0; kx < 3; kx++){
            const ulonglong2* wp = reinterpret_cast<const ulonglong2*>(&sw[(c*9 + ky*3 + kx)*16]);
#pragma unroll
            for (int g = 0; g < 8; g++){
                ulonglong2 wv = wp[g];
#pragma unroll
                for (int pp = 0; pp < 4; pp++){
                    fma2(acc[pp][2*g],   du[ky][kx+pp], wv.x);
                    fma2(acc[pp][2*g+1], du[ky][kx+pp], wv.y);
                }
            }
        }
    }

    // heads: per-pixel full 32-channel dot products
    float l0[4], l1[4], r0[4], r1[4], r2[4], r3[4];
#pragma unroll
    for (int pp = 0; pp < 4; pp++){
        l0[pp] = sb41[0]; l1[pp] = sb41[1];
        r0[pp] = sb42[0]; r1[pp] = sb42[1]; r2[pp] = sb42[2]; r3[pp] = sb42[3];
    }
#pragma unroll
    for (int q = 0; q < 16; q++){
        float wA0 = sw41[2*q],    wA1 = sw41[2*q+1];
        float wB0 = sw41[32+2*q], wB1 = sw41[32+2*q+1];
        float q00 = sw42[2*q],    q01 = sw42[2*q+1];
        float q10 = sw42[32+2*q], q11 = sw42[32+2*q+1];
        float q20 = sw42[64+2*q], q21 = sw42[64+2*q+1];
        float q30 = sw42[96+2*q], q31 = sw42[96+2*q+1];
        float alo = sp[2*q], ahi = sp[2*q+1];
#pragma unroll
        for (int pp = 0; pp < 4; pp++){
            float hA, hB; unpack2(acc[pp][q], hA, hB);
            hA = hA > 0.f ? hA : alo*hA;
            hB = hB > 0.f ? hB : ahi*hB;
            l0[pp] = fmaf(hA, wA0, fmaf(hB, wA1, l0[pp]));
            l1[pp] = fmaf(hA, wB0, fmaf(hB, wB1, l1[pp]));
            r0[pp] = fmaf(hA, q00, fmaf(hB, q01, r0[pp]));
            r1[pp] = fmaf(hA, q10, fmaf(hB, q11, r1[pp]));
            r2[pp] = fmaf(hA, q20, fmaf(hB, q21, r2[pp]));
            r3[pp] = fmaf(hA, q30, fmaf(hB, q31, r3[pp]));
        }
    }
    if (oy < H3D){
#pragma unroll
        for (int pp = 0; pp < 4; pp++){
            int x = x0 + pp;
            if (x >= W3D) continue;
            float prob = 1.f / (1.f + expf(l0[pp] - l1[pp]));
            if (prob >= THRESH_V){
                int pos = atomicAdd(&g_cnt[bb], 1);
                if (pos < NPIX){
                    g_cand[bb*NPIX + pos]    = (oy << 16) | x;
                    g_cand_sc[bb*NPIX + pos] = prob;
                    g_cand_reg[bb*NPIX + pos] = make_float4(r0[pp], r1[pp], r2[pp], r3[pp]);
                }
            }
        }
    }
}

// ============================================================
// K4: per-batch iterative argmax NMS on unordered candidate list.
// Tie-break (score desc, packed xy asc) == pixel-index order.
// IoU>0.5 for 12x12 stride-2 boxes  <=>  |dx|<=1 && |dy|<=1.
// ============================================================
__global__ void k4_nms(float* __restrict__ out)
{
    const int NT = 256;
    int bb = blockIdx.x, tid = threadIdx.x;
    int lane = tid & 31, wrp = tid >> 5;

    __shared__ float s_sc[CAP];
    __shared__ int   s_xy[CAP];
    __shared__ float w_s[8];
    __shared__ int   w_xy[8], w_i[8];
    __shared__ float sh_best;
    __shared__ int   sh_j, sh_xy;

    int count = g_cnt[bb];
    if (count > NPIX) count = NPIX;
    bool insh = (count <= CAP);
    float* scp;
    const int* xyp;
    if (insh){
        for (int i = tid; i < count; i += NT){
            s_sc[i] = g_cand_sc[bb*NPIX + i];
            s_xy[i] = g_cand[bb*NPIX + i];
        }
        scp = s_sc; xyp = s_xy;
    } else {
        scp = g_cand_sc + bb*NPIX;
        xyp = g_cand + bb*NPIX;
    }
    __syncthreads();

    for (int k = 0; k < KPICKS; k++){
        float bs = -INFINITY; int bxy = 0x7fffffff; int bi = -1;
        for (int i = tid; i < count; i += NT){
            float v = scp[i]; int xy = xyp[i];
            if (v > bs || (v == bs && xy < bxy)){ bs = v; bxy = xy; bi = i; }
        }
#pragma unroll
        for (int off = 16; off > 0; off >>= 1){
            float vs  = __shfl_down_sync(0xffffffffu, bs,  off);
            int   vxy = __shfl_down_sync(0xffffffffu, bxy, off);
            int   vi  = __shfl_down_sync(0xffffffffu, bi,  off);
            if (vs > bs || (vs == bs && vxy < bxy)){ bs = vs; bxy = vxy; bi = vi; }
        }
        if (lane == 0){ w_s[wrp] = bs; w_xy[wrp] = bxy; w_i[wrp] = bi; }
        __syncthreads();
        if (tid == 0){
            float cs = w_s[0]; int cxy = w_xy[0], ci = w_i[0];
#pragma unroll
            for (int t = 1; t < 8; t++){
                if (w_s[t] > cs || (w_s[t] == cs && w_xy[t] < cxy)){
                    cs = w_s[t]; cxy = w_xy[t]; ci = w_i[t];
                }
            }
            sh_best = cs; sh_j = ci; sh_xy = cxy;
        }
        __syncthreads();
        float best = sh_best; int j = sh_j; int jxy = sh_xy;

        if (!(best > -0.5e30f) || j < 0){
            int n0 = (KPICKS - k) * 5;
            float* o0 = out + ((size_t)bb*KPICKS + k)*5;
            for (int t = tid; t < n0; t += NT) o0[t] = 0.f;
            break;
        }

        int jx = jxy & 0xffff, jy = jxy >> 16;
        for (int i = tid; i < count; i += NT){
            int p = xyp[i];
            int dx = (p & 0xffff) - jx; dx = dx < 0 ? -dx : dx;
            int dy = (p >> 16)    - jy; dy = dy < 0 ? -dy : dy;
            if (dx <= 1 && dy <= 1) scp[i] = NEGV;
        }
        if (tid == 0){
            float x1 = 2.f*jx + 1.f,  y1 = 2.f*jy + 1.f;
            float x2 = 2.f*jx + 12.f, y2 = 2.f*jy + 12.f;
            float4 r = g_cand_reg[bb*NPIX + j];
            float q1 = fmaf(r.x, 11.f, x1);
            float q2 = fmaf(r.y, 11.f, y1);
            float q3 = fmaf(r.z, 11.f, x2);
            float q4 = fmaf(r.w, 11.f, y2);
            float rw = q3 - q1, rh = q4 - q2;
            float l = fmaxf(rw, rh);
            float nx1 = q1 + rw*0.5f - l*0.5f;
            float ny1 = q2 + rh*0.5f - l*0.5f;
            float* o = out + ((size_t)bb*KPICKS + k)*5;
            o[0] = nx1; o[1] = ny1; o[2] = nx1 + l; o[3] = ny1 + l; o[4] = best;
        }
        __syncthreads();
    }
}

// ============================================================
extern "C" void kernel_launch(void* const* d_in, const int* in_sizes, int n_in,
                              void* d_out, int out_size)
{
    const float* im   = (const float*)d_in[0];
    const float* c1w  = (const float*)d_in[1];
    const float* c1b  = (const float*)d_in[2];
    const float* p1   = (const float*)d_in[3];
    const float* c2w  = (const float*)d_in[4];
    const float* c2b  = (const float*)d_in[5];
    const float* p2   = (const float*)d_in[6];
    const float* c3w  = (const float*)d_in[7];
    const float* c3b  = (const float*)d_in[8];
    const float* p3   = (const float*)d_in[9];
    const float* c41w = (const float*)d_in[10];
    const float* c41b = (const float*)d_in[11];
    const float* c42w = (const float*)d_in[12];
    const float* c42b = (const float*)d_in[13];
    float* out = (float*)d_out;

    dim3 blk(32, 8, 1);
    dim3 g1(8, 24, BB);   // 32 px * 8 rows, 255x191
    dim3 g2(2, 24, BB);   // 128 px * 8 rows, covers 253x189(+pad)
    dim3 g3(2, 24, BB);   // 128 px * 8 rows, covers 251x187(+pad)

    k0_zero<<<1, 32>>>();
    k1_conv1_pool<<<g1, blk>>>(im, c1w, c1b, p1);
    k2_conv2<<<g2, blk>>>(c2w, c2b, p2);
    k3_conv3_heads<<<g3, blk>>>(c3w, c3b, p3, c41w, c41b, c42w, c42b);
    k4_nms<<<BB, 256>>>(out);
}

// round 5
// speedup vs baseline: 1.0237x; 1.0237x over previous
#include <cuda_runtime.h>
#include <math.h>

typedef unsigned long long ull;

// ---- problem constants ----
#define BB  16
#define HH  384
#define WW  512
#define HPP 191
#define WPP 255
#define H2D 189
#define W2D 253
#define H3D 187
#define W3D 251
#define NPIX (H3D*W3D)   // 46937
#define NEGV (-1e30f)
#define THRESH_V 0.6f
#define KPICKS 128
#define CAP 5600
#define SP  260          // padded row stride (mult of 4)
#define PH  196          // padded plane height

// staging layout offsets (in ull)
#define W1OFF 0
#define W1N   135
#define W2OFF 135
#define W2N   720
#define W3OFF 855
#define W3N   2304
#define WTOT  3159

// ---- scratch (zero-initialized device globals; padding stays deterministic) ----
__device__ __align__(16) float  g_pool[BB*10*PH*SP];
__device__ __align__(16) float  g_h2[BB*16*PH*SP];
__device__ __align__(16) ull    g_stage[WTOT];
__device__ int    g_cnt[BB];
__device__ int    g_cand[BB*NPIX];      // packed (y<<16)|x
__device__ float  g_cand_sc[BB*NPIX];
__device__ float4 g_cand_reg[BB*NPIX];

// ---- packed oc-pair weights in constant memory (uniform-path operands) ----
__constant__ ull c_w1[W1N];   // [(c*9+k)*5  + q]
__constant__ ull c_w2[W2N];   // [(c*9+k)*8  + q]
__constant__ ull c_w3[W3N];   // [(c*9+k)*16 + q]

// ---- f32x2 helpers ----
__device__ __forceinline__ ull pack2(float lo, float hi){
    ull r; asm("mov.b64 %0, {%1, %2};" : "=l"(r) : "f"(lo), "f"(hi)); return r;
}
__device__ __forceinline__ void unpack2(ull v, float &lo, float &hi){
    asm("mov.b64 {%0, %1}, %2;" : "=f"(lo), "=f"(hi) : "l"(v));
}
__device__ __forceinline__ void fma2(ull &d, ull a, ull b){
    asm("fma.rn.f32x2 %0, %1, %2, %0;" : "+l"(d) : "l"(a), "l"(b));
}

// ============================================================
// K0: pack weights into oc-pair layout (staged for const copy)
// and zero candidate counters
// ============================================================
__global__ void k0_pack(const float* __restrict__ w1,
                        const float* __restrict__ w2,
                        const float* __restrict__ w3)
{
    int tid = threadIdx.x;
    if (tid < BB) g_cnt[tid] = 0;
    for (int i = tid; i < W1N; i += 256){
        int ck = i / 5, q = i % 5;
        g_stage[W1OFF + i] = pack2(w1[(2*q)*27 + ck], w1[(2*q+1)*27 + ck]);
    }
    for (int i = tid; i < W2N; i += 256){
        int ck = i >> 3, q = i & 7;
        g_stage[W2OFF + i] = pack2(w2[(2*q)*90 + ck], w2[(2*q+1)*90 + ck]);
    }
    for (int i = tid; i < W3N; i += 256){
        int ck = i >> 4, q = i & 15;
        g_stage[W3OFF + i] = pack2(w3[(2*q)*144 + ck], w3[(2*q+1)*144 + ck]);
    }
}

// ============================================================
// K1: normalize + conv1(3x3,3->10) + PReLU + maxpool2x2
// 1 thread = 1 pooled pixel (4 conv px), oc-pair packing
// ============================================================
__global__ __launch_bounds__(256) void k1_conv1_pool(const float* __restrict__ im,
                              const float* __restrict__ b,
                              const float* __restrict__ p)
{
    __shared__ float sb[10], sp[10];
    int tid = threadIdx.y * 32 + threadIdx.x;
    if (tid < 10){ sb[tid] = b[tid]; sp[tid] = p[tid]; }
    __syncthreads();

    int ox = blockIdx.x * 32 + threadIdx.x;
    int oy = blockIdx.y * 8  + threadIdx.y;
    int bb = blockIdx.z;
    if (ox >= WPP || oy >= HPP) return;

    ull acc[4][5];
#pragma unroll
    for (int q = 0; q < 5; q++){
        ull bi = pack2(sb[2*q], sb[2*q+1]);
        acc[0][q] = bi; acc[1][q] = bi; acc[2][q] = bi; acc[3][q] = bi;
    }

#pragma unroll
    for (int c = 0; c < 3; c++){
        const float* base = im + ((bb*3 + c)*HH + 2*oy)*WW + 2*ox;
        ull du[4][4];
#pragma unroll
        for (int r = 0; r < 4; r++){
            float2 u01 = *reinterpret_cast<const float2*>(base + r*WW);
            float2 u23 = *reinterpret_cast<const float2*>(base + r*WW + 2);
            float v0 = (u01.x - 127.5f)*0.0078125f;
            float v1 = (u01.y - 127.5f)*0.0078125f;
            float v2 = (u23.x - 127.5f)*0.0078125f;
            float v3 = (u23.y - 127.5f)*0.0078125f;
            du[r][0] = pack2(v0,v0); du[r][1] = pack2(v1,v1);
            du[r][2] = pack2(v2,v2); du[r][3] = pack2(v3,v3);
        }
#pragma unroll
        for (int ky = 0; ky < 3; ky++)
#pragma unroll
        for (int kx = 0; kx < 3; kx++){
            const ull* wq = &c_w1[(c*9 + ky*3 + kx)*5];
#pragma unroll
            for (int q = 0; q < 5; q++){
                ull wv = wq[q];
                fma2(acc[0][q], du[ky  ][kx  ], wv);
                fma2(acc[1][q], du[ky  ][kx+1], wv);
                fma2(acc[2][q], du[ky+1][kx  ], wv);
                fma2(acc[3][q], du[ky+1][kx+1], wv);
            }
        }
    }
#pragma unroll
    for (int q = 0; q < 5; q++){
        float h[4][2];
#pragma unroll
        for (int pp = 0; pp < 4; pp++) unpack2(acc[pp][q], h[pp][0], h[pp][1]);
#pragma unroll
        for (int s = 0; s < 2; s++){
            int oc = 2*q + s;
            float al = sp[oc];
            float m = -INFINITY;
#pragma unroll
            for (int pp = 0; pp < 4; pp++){
                float v = h[pp][s];
                v = v > 0.f ? v : al*v;
                m = fmaxf(m, v);
            }
            g_pool[((bb*10 + oc)*PH + oy)*SP + ox] = m;
        }
    }
}

// ============================================================
// K2: conv2(3x3,10->16) + PReLU
// 1 thread = 4 px, 8 ocpairs; weights via constant/uniform path
// ============================================================
__global__ __launch_bounds__(256) void k2_conv2(const float* __restrict__ b,
                         const float* __restrict__ p)
{
    __shared__ float sb[16], sp[16];
    int tid = threadIdx.y * 32 + threadIdx.x;
    if (tid < 16){ sb[tid] = b[tid]; sp[tid] = p[tid]; }
    __syncthreads();

    int x0 = blockIdx.x * 128 + threadIdx.x * 4;  // <= 252; reads <= 257 < SP
    int oy = blockIdx.y * 8   + threadIdx.y;      // <= 191; reads rows <= 193 < PH
    int bb = blockIdx.z;

    ull acc[4][8];
#pragma unroll
    for (int q = 0; q < 8; q++){
        ull bi = pack2(sb[2*q], sb[2*q+1]);
        acc[0][q] = bi; acc[1][q] = bi; acc[2][q] = bi; acc[3][q] = bi;
    }

    for (int c = 0; c < 10; c++){
        const float* base = g_pool + ((bb*10 + c)*PH + oy)*SP + x0;
        ull du[3][6];
#pragma unroll
        for (int r = 0; r < 3; r++){
            float4 a4 = *reinterpret_cast<const float4*>(base + r*SP);
            float2 b2 = *reinterpret_cast<const float2*>(base + r*SP + 4);
            du[r][0] = pack2(a4.x,a4.x); du[r][1] = pack2(a4.y,a4.y);
            du[r][2] = pack2(a4.z,a4.z); du[r][3] = pack2(a4.w,a4.w);
            du[r][4] = pack2(b2.x,b2.x); du[r][5] = pack2(b2.y,b2.y);
        }
#pragma unroll
        for (int ky = 0; ky < 3; ky++)
#pragma unroll
        for (int kx = 0; kx < 3; kx++){
            const ull* wq = &c_w2[(c*9 + ky*3 + kx)*8];
#pragma unroll
            for (int q = 0; q < 8; q++){
                ull wv = wq[q];
#pragma unroll
                for (int pp = 0; pp < 4; pp++)
                    fma2(acc[pp][q], du[ky][kx+pp], wv);
            }
        }
    }
#pragma unroll
    for (int q = 0; q < 8; q++){
        float v[4][2];
#pragma unroll
        for (int pp = 0; pp < 4; pp++) unpack2(acc[pp][q], v[pp][0], v[pp][1]);
#pragma unroll
        for (int s = 0; s < 2; s++){
            int oc = 2*q + s;
            float al = sp[oc];
            float4 o;
            float t0 = v[0][s]; o.x = t0 > 0.f ? t0 : al*t0;
            float t1 = v[1][s]; o.y = t1 > 0.f ? t1 : al*t1;
            float t2 = v[2][s]; o.z = t2 > 0.f ? t2 : al*t2;
            float t3 = v[3][s]; o.w = t3 > 0.f ? t3 : al*t3;
            *reinterpret_cast<float4*>(&g_h2[((bb*16 + oc)*PH + oy)*SP + x0]) = o;
        }
    }
}

// ============================================================
// K3: conv3(3x3,16->32)+PReLU + fused 1x1 heads + append
// 1 thread = 4 px, 16 ocpairs; weights via constant/uniform path
// ============================================================
__global__ __launch_bounds__(256) void k3_conv3_heads(const float* __restrict__ b3,
                               const float* __restrict__ p3,
                               const float* __restrict__ w41, const float* __restrict__ b41,
                               const float* __restrict__ w42, const float* __restrict__ b42)
{
    __shared__ float sb[32], sp[32];
    __shared__ float sw41[64], sw42[128], sb41[2], sb42[4];
    int tid = threadIdx.y * 32 + threadIdx.x;
    if (tid < 32){ sb[tid] = b3[tid]; sp[tid] = p3[tid]; }
    if (tid < 64)  sw41[tid] = w41[tid];
    if (tid < 128) sw42[tid] = w42[tid];
    if (tid < 2)   sb41[tid] = b41[tid];
    if (tid < 4)   sb42[tid] = b42[tid];
    __syncthreads();

    int x0 = blockIdx.x * 128 + threadIdx.x * 4;  // <= 252; reads <= 257 < SP
    int oy = blockIdx.y * 8   + threadIdx.y;      // <= 191; reads rows <= 193 < PH
    int bb = blockIdx.z;

    ull acc[4][16];
#pragma unroll
    for (int q = 0; q < 16; q++){
        ull bi = pack2(sb[2*q], sb[2*q+1]);
        acc[0][q] = bi; acc[1][q] = bi; acc[2][q] = bi; acc[3][q] = bi;
    }

    for (int c = 0; c < 16; c++){
        const float* base = g_h2 + ((bb*16 + c)*PH + oy)*SP + x0;
        ull du[3][6];
#pragma unroll
        for (int r = 0; r < 3; r++){
            float4 a4 = *reinterpret_cast<const float4*>(base + r*SP);
            float2 b2 = *reinterpret_cast<const float2*>(base + r*SP + 4);
            du[r][0] = pack2(a4.x,a4.x); du[r][1] = pack2(a4.y,a4.y);
            du[r][2] = pack2(a4.z,a4.z); du[r][3] = pack2(a4.w,a4.w);
            du[r][4] = pack2(b2.x,b2.x); du[r][5] = pack2(b2.y,b2.y);
        }
#pragma unroll
        for (int ky = 0; ky < 3; ky++)
#pragma unroll
        for (int kx = 0; kx < 3; kx++){
            const ull* wq = &c_w3[(c*9 + ky*3 + kx)*16];
#pragma unroll
            for (int q = 0; q < 16; q++){
                ull wv = wq[q];
#pragma unroll
                for (int pp = 0; pp < 4; pp++)
                    fma2(acc[pp][q], du[ky][kx+pp], wv);
            }
        }
    }

    // heads: per-pixel full 32-channel dot products
    float l0[4], l1[4], r0[4], r1[4], r2[4], r3[4];
#pragma unroll
    for (int pp = 0; pp < 4; pp++){
        l0[pp] = sb41[0]; l1[pp] = sb41[1];
        r0[pp] = sb42[0]; r1[pp] = sb42[1]; r2[pp] = sb42[2]; r3[pp] = sb42[3];
    }
#pragma unroll
    for (int q = 0; q < 16; q++){
        float wA0 = sw41[2*q],    wA1 = sw41[2*q+1];
        float wB0 = sw41[32+2*q], wB1 = sw41[32+2*q+1];
        float q00 = sw42[2*q],    q01 = sw42[2*q+1];
        float q10 = sw42[32+2*q], q11 = sw42[32+2*q+1];
        float q20 = sw42[64+2*q], q21 = sw42[64+2*q+1];
        float q30 = sw42[96+2*q], q31 = sw42[96+2*q+1];
        float alo = sp[2*q], ahi = sp[2*q+1];
#pragma unroll
        for (int pp = 0; pp < 4; pp++){
            float hA, hB; unpack2(acc[pp][q], hA, hB);
            hA = hA > 0.f ? hA : alo*hA;
            hB = hB > 0.f ? hB : ahi*hB;
            l0[pp] = fmaf(hA, wA0, fmaf(hB, wA1, l0[pp]));
            l1[pp] = fmaf(hA, wB0, fmaf(hB, wB1, l1[pp]));
            r0[pp] = fmaf(hA, q00, fmaf(hB, q01, r0[pp]));
            r1[pp] = fmaf(hA, q10, fmaf(hB, q11, r1[pp]));
            r2[pp] = fmaf(hA, q20, fmaf(hB, q21, r2[pp]));
            r3[pp] = fmaf(hA, q30, fmaf(hB, q31, r3[pp]));
        }
    }
    if (oy < H3D){
#pragma unroll
        for (int pp = 0; pp < 4; pp++){
            int x = x0 + pp;
            if (x >= W3D) continue;
            float prob = 1.f / (1.f + expf(l0[pp] - l1[pp]));
            if (prob >= THRESH_V){
                int pos = atomicAdd(&g_cnt[bb], 1);
                if (pos < NPIX){
                    g_cand[bb*NPIX + pos]    = (oy << 16) | x;
                    g_cand_sc[bb*NPIX + pos] = prob;
                    g_cand_reg[bb*NPIX + pos] = make_float4(r0[pp], r1[pp], r2[pp], r3[pp]);
                }
            }
        }
    }
}

// ============================================================
// K4: per-batch iterative argmax NMS on unordered candidate list.
// Tie-break (score desc, packed xy asc) == pixel-index order.
// IoU>0.5 for 12x12 stride-2 boxes  <=>  |dx|<=1 && |dy|<=1.
// ============================================================
__global__ void k4_nms(float* __restrict__ out)
{
    const int NT = 256;
    int bb = blockIdx.x, tid = threadIdx.x;
    int lane = tid & 31, wrp = tid >> 5;

    __shared__ float s_sc[CAP];
    __shared__ int   s_xy[CAP];
    __shared__ float w_s[8];
    __shared__ int   w_xy[8], w_i[8];
    __shared__ float sh_best;
    __shared__ int   sh_j, sh_xy;

    int count = g_cnt[bb];
    if (count > NPIX) count = NPIX;
    bool insh = (count <= CAP);
    float* scp;
    const int* xyp;
    if (insh){
        for (int i = tid; i < count; i += NT){
            s_sc[i] = g_cand_sc[bb*NPIX + i];
            s_xy[i] = g_cand[bb*NPIX + i];
        }
        scp = s_sc; xyp = s_xy;
    } else {
        scp = g_cand_sc + bb*NPIX;
        xyp = g_cand + bb*NPIX;
    }
    __syncthreads();

    for (int k = 0; k < KPICKS; k++){
        float bs = -INFINITY; int bxy = 0x7fffffff; int bi = -1;
        for (int i = tid; i < count; i += NT){
            float v = scp[i]; int xy = xyp[i];
            if (v > bs || (v == bs && xy < bxy)){ bs = v; bxy = xy; bi = i; }
        }
#pragma unroll
        for (int off = 16; off > 0; off >>= 1){
            float vs  = __shfl_down_sync(0xffffffffu, bs,  off);
            int   vxy = __shfl_down_sync(0xffffffffu, bxy, off);
            int   vi  = __shfl_down_sync(0xffffffffu, bi,  off);
            if (vs > bs || (vs == bs && vxy < bxy)){ bs = vs; bxy = vxy; bi = vi; }
        }
        if (lane == 0){ w_s[wrp] = bs; w_xy[wrp] = bxy; w_i[wrp] = bi; }
        __syncthreads();
        if (tid == 0){
            float cs = w_s[0]; int cxy = w_xy[0], ci = w_i[0];
#pragma unroll
            for (int t = 1; t < 8; t++){
                if (w_s[t] > cs || (w_s[t] == cs && w_xy[t] < cxy)){
                    cs = w_s[t]; cxy = w_xy[t]; ci = w_i[t];
                }
            }
            sh_best = cs; sh_j = ci; sh_xy = cxy;
        }
        __syncthreads();
        float best = sh_best; int j = sh_j; int jxy = sh_xy;

        if (!(best > -0.5e30f) || j < 0){
            int n0 = (KPICKS - k) * 5;
            float* o0 = out + ((size_t)bb*KPICKS + k)*5;
            for (int t = tid; t < n0; t += NT) o0[t] = 0.f;
            break;
        }

        int jx = jxy & 0xffff, jy = jxy >> 16;
        for (int i = tid; i < count; i += NT){
            int p = xyp[i];
            int dx = (p & 0xffff) - jx; dx = dx < 0 ? -dx : dx;
            int dy = (p >> 16)    - jy; dy = dy < 0 ? -dy : dy;
            if (dx <= 1 && dy <= 1) scp[i] = NEGV;
        }
        if (tid == 0){
            float x1 = 2.f*jx + 1.f,  y1 = 2.f*jy + 1.f;
            float x2 = 2.f*jx + 12.f, y2 = 2.f*jy + 12.f;
            float4 r = g_cand_reg[bb*NPIX + j];
            float q1 = fmaf(r.x, 11.f, x1);
            float q2 = fmaf(r.y, 11.f, y1);
            float q3 = fmaf(r.z, 11.f, x2);
            float q4 = fmaf(r.w, 11.f, y2);
            float rw = q3 - q1, rh = q4 - q2;
            float l = fmaxf(rw, rh);
            float nx1 = q1 + rw*0.5f - l*0.5f;
            float ny1 = q2 + rh*0.5f - l*0.5f;
            float* o = out + ((size_t)bb*KPICKS + k)*5;
            o[0] = nx1; o[1] = ny1; o[2] = nx1 + l; o[3] = ny1 + l; o[4] = best;
        }
        __syncthreads();
    }
}

// ============================================================
extern "C" void kernel_launch(void* const* d_in, const int* in_sizes, int n_in,
                              void* d_out, int out_size)
{
    const float* im   = (const float*)d_in[0];
    const float* c1w  = (const float*)d_in[1];
    const float* c1b  = (const float*)d_in[2];
    const float* p1   = (const float*)d_in[3];
    const float* c2w  = (const float*)d_in[4];
    const float* c2b  = (const float*)d_in[5];
    const float* p2   = (const float*)d_in[6];
    const float* c3w  = (const float*)d_in[7];
    const float* c3b  = (const float*)d_in[8];
    const float* p3   = (const float*)d_in[9];
    const float* c41w = (const float*)d_in[10];
    const float* c41b = (const float*)d_in[11];
    const float* c42w = (const float*)d_in[12];
    const float* c42b = (const float*)d_in[13];
    float* out = (float*)d_out;

    // stage packed weights, then copy into constant banks (async D2D, capturable)
    k0_pack<<<1, 256>>>(c1w, c2w, c3w);
    void* stage_ptr = nullptr;
    cudaGetSymbolAddress(&stage_ptr, g_stage);
    const char* sp8 = (const char*)stage_ptr;
    cudaMemcpyToSymbolAsync(c_w1, sp8 + (size_t)W1OFF*8, (size_t)W1N*8, 0,
                            cudaMemcpyDeviceToDevice, 0);
    cudaMemcpyToSymbolAsync(c_w2, sp8 + (size_t)W2OFF*8, (size_t)W2N*8, 0,
                            cudaMemcpyDeviceToDevice, 0);
    cudaMemcpyToSymbolAsync(c_w3, sp8 + (size_t)W3OFF*8, (size_t)W3N*8, 0,
                            cudaMemcpyDeviceToDevice, 0);

    dim3 blk(32, 8, 1);
    dim3 g1(8, 24, BB);   // 32 px * 8 rows, 255x191
    dim3 g2(2, 24, BB);   // 128 px * 8 rows, covers 253x189(+pad)
    dim3 g3(2, 24, BB);   // 128 px * 8 rows, covers 251x187(+pad)

    k1_conv1_pool<<<g1, blk>>>(im, c1b, p1);
    k2_conv2<<<g2, blk>>>(c2b, p2);
    k3_conv3_heads<<<g3, blk>>>(c3b, p3, c41w, c41b, c42w, c42b);
    k4_nms<<<BB, 256>>>(out);
}